// round 10
// baseline (speedup 1.0000x reference)
#include <cuda_runtime.h>
#include <cuda_bf16.h>
#include <stdint.h>

#define NMAX 50000
#define HH   128
#define EMAX 800000
#define CC   40

// ---------------- scratch (static device arrays; referenced directly in kernels) ----------------
__device__ int   g_is32;                  // 1 if edge_index is int32, 0 if int64
__device__ int   g_degi  [NMAX];
__device__ int   g_off   [NMAX + 1];
__device__ int   g_cursor[NMAX];
__device__ float g_dinv  [NMAX];
__device__ int   g_es    [EMAX];          // src sorted by dst
__device__ float g_en    [EMAX];          // norm sorted by dst
__device__ __align__(16) float g_H [NMAX * HH];
__device__ __align__(16) float g_X1[NMAX * HH];
__device__ __align__(16) float g_X2[NMAX * HH];

// ---------------- dtype detection + edge access ----------------
__global__ void detect_k(const void* ei, int E, int n) {
    const long long* p = (const long long*)ei;
    int is32 = 0;
    int lim = (E < 64) ? E : 64;
    for (int i = 0; i < lim; i++) {
        long long v = p[i];
        if (v < 0 || v >= (long long)n) { is32 = 1; break; }
    }
    g_is32 = is32;
}

__device__ __forceinline__ int edge_src(const void* ei, int E, int e) {
    return g_is32 ? ((const int*)ei)[e] : (int)((const long long*)ei)[e];
}
__device__ __forceinline__ int edge_dst(const void* ei, int E, int e) {
    return g_is32 ? ((const int*)ei)[E + e] : (int)((const long long*)ei)[E + e];
}

// ---------------- CSR build ----------------
__global__ void zero_ints_k(int n) {
    int i = blockIdx.x * blockDim.x + threadIdx.x;
    if (i < n) { g_degi[i] = 0; g_cursor[i] = 0; }
}

__global__ void hist_k(const void* ei, int E) {
    int e = blockIdx.x * blockDim.x + threadIdx.x;
    if (e < E) atomicAdd(&g_degi[edge_dst(ei, E, e)], 1);
}

__global__ void dinv_k(int n) {
    int i = blockIdx.x * blockDim.x + threadIdx.x;
    if (i < n) g_dinv[i] = rsqrtf((float)(g_degi[i] + 1));  // +1 self loop
}

// single-block exclusive scan over degrees
__global__ void scan_k(int n) {
    __shared__ int shw[32];
    __shared__ int carry, btot;
    int tid = threadIdx.x, lane = tid & 31, wid = tid >> 5;
    if (tid == 0) carry = 0;
    __syncthreads();
    for (int base = 0; base < n; base += 1024) {
        int i = base + tid;
        int d = (i < n) ? g_degi[i] : 0;
        int incl = d;
        #pragma unroll
        for (int o = 1; o < 32; o <<= 1) {
            int v = __shfl_up_sync(0xffffffffu, incl, o);
            if (lane >= o) incl += v;
        }
        if (lane == 31) shw[wid] = incl;
        __syncthreads();
        if (wid == 0) {
            int w = shw[lane];
            int wi = w;
            #pragma unroll
            for (int o = 1; o < 32; o <<= 1) {
                int v = __shfl_up_sync(0xffffffffu, wi, o);
                if (lane >= o) wi += v;
            }
            shw[lane] = wi - w;
            if (lane == 31) btot = wi;
        }
        __syncthreads();
        if (i < n) g_off[i] = carry + shw[wid] + incl - d;
        __syncthreads();
        if (tid == 0) carry += btot;
        __syncthreads();
    }
    if (tid == 0) g_off[n] = carry;
}

__global__ void bucket_k(const void* ei, int E) {
    int e = blockIdx.x * blockDim.x + threadIdx.x;
    if (e >= E) return;
    int s = edge_src(ei, E, e);
    int d = edge_dst(ei, E, e);
    int pos = g_off[d] + atomicAdd(&g_cursor[d], 1);
    g_es[pos] = s;
    g_en[pos] = g_dinv[s] * g_dinv[d];
}

// ---------------- tensor-core GEMM (3xTF32 split): g_H[n,128] = src @ W ----------------
#define MMA_TF32(c, a, b) \
    asm volatile("mma.sync.aligned.m16n8k8.row.col.f32.tf32.tf32.f32 " \
        "{%0,%1,%2,%3}, {%4,%5,%6,%7}, {%8,%9}, {%0,%1,%2,%3};" \
        : "+f"((c)[0]), "+f"((c)[1]), "+f"((c)[2]), "+f"((c)[3]) \
        : "r"((a)[0]), "r"((a)[1]), "r"((a)[2]), "r"((a)[3]), \
          "r"((b)[0]), "r"((b)[1]))

__device__ __forceinline__ void split_tf32(float x, float& hi, float& lo) {
    uint32_t hb;
    asm("cvt.rna.tf32.f32 %0, %1;" : "=r"(hb) : "f"(x));
    hi = __uint_as_float(hb);
    float r = x - hi;
    uint32_t lb;
    asm("cvt.rna.tf32.f32 %0, %1;" : "=r"(lb) : "f"(r));
    lo = __uint_as_float(lb);
}

// src_sel: 0 = external X, 1 = g_X1, 2 = g_X2
__global__ __launch_bounds__(256)
void gemm_tc_k(const float* __restrict__ Xin, const float* __restrict__ W,
               int src_sel, int n) {
    const float* __restrict__ A = (src_sel == 0) ? Xin : (src_sel == 1 ? g_X1 : g_X2);
    float* __restrict__ C = g_H;

    __shared__ float As_hi[128][20], As_lo[128][20];   // [m][k], pad 4
    __shared__ float Bs_hi[16][132], Bs_lo[16][132];   // [k][n], pad 4

    const int tid   = threadIdx.x;
    const int lane  = tid & 31, wid = tid >> 5;
    const int gid   = lane >> 2, tig = lane & 3;
    const int warpM = (wid >> 2) * 64;   // 0 or 64
    const int warpN = (wid & 3) * 32;    // 0,32,64,96
    const int row0  = blockIdx.x * 128;

    float acc[4][4][4] = {};             // [mt][nt][c-reg]

    for (int c16 = 0; c16 < HH; c16 += 16) {
        // A tile 128x16 -> hi/lo smem
        #pragma unroll
        for (int j = 0; j < 2; j++) {
            int idx = tid + j * 256;
            int r = idx >> 2, q = idx & 3;
            float4 v = make_float4(0.f, 0.f, 0.f, 0.f);
            if (row0 + r < n) v = *(const float4*)(A + (size_t)(row0 + r) * HH + c16 + q * 4);
            float xs[4] = {v.x, v.y, v.z, v.w};
            #pragma unroll
            for (int u = 0; u < 4; u++) {
                float hi, lo; split_tf32(xs[u], hi, lo);
                As_hi[r][q * 4 + u] = hi;
                As_lo[r][q * 4 + u] = lo;
            }
        }
        // W tile 16x128 -> hi/lo smem
        #pragma unroll
        for (int j = 0; j < 2; j++) {
            int idx = tid + j * 256;
            int kr = idx >> 5, cq = idx & 31;
            float4 v = *(const float4*)(W + (size_t)(c16 + kr) * HH + cq * 4);
            float xs[4] = {v.x, v.y, v.z, v.w};
            #pragma unroll
            for (int u = 0; u < 4; u++) {
                float hi, lo; split_tf32(xs[u], hi, lo);
                Bs_hi[kr][cq * 4 + u] = hi;
                Bs_lo[kr][cq * 4 + u] = lo;
            }
        }
        __syncthreads();

        #pragma unroll
        for (int ks = 0; ks < 2; ks++) {
            int kk = ks * 8;
            uint32_t bh[4][2], bl[4][2];
            #pragma unroll
            for (int nt = 0; nt < 4; nt++) {
                int nn = warpN + nt * 8 + gid;
                bh[nt][0] = __float_as_uint(Bs_hi[kk + tig    ][nn]);
                bh[nt][1] = __float_as_uint(Bs_hi[kk + tig + 4][nn]);
                bl[nt][0] = __float_as_uint(Bs_lo[kk + tig    ][nn]);
                bl[nt][1] = __float_as_uint(Bs_lo[kk + tig + 4][nn]);
            }
            #pragma unroll
            for (int mt = 0; mt < 4; mt++) {
                int mm = warpM + mt * 16;
                uint32_t ah[4], al[4];
                ah[0] = __float_as_uint(As_hi[mm + gid    ][kk + tig    ]);
                ah[1] = __float_as_uint(As_hi[mm + gid + 8][kk + tig    ]);
                ah[2] = __float_as_uint(As_hi[mm + gid    ][kk + tig + 4]);
                ah[3] = __float_as_uint(As_hi[mm + gid + 8][kk + tig + 4]);
                al[0] = __float_as_uint(As_lo[mm + gid    ][kk + tig    ]);
                al[1] = __float_as_uint(As_lo[mm + gid + 8][kk + tig    ]);
                al[2] = __float_as_uint(As_lo[mm + gid    ][kk + tig + 4]);
                al[3] = __float_as_uint(As_lo[mm + gid + 8][kk + tig + 4]);
                #pragma unroll
                for (int nt = 0; nt < 4; nt++) {
                    MMA_TF32(acc[mt][nt], ah, bh[nt]);   // Ah*Bh
                    MMA_TF32(acc[mt][nt], ah, bl[nt]);   // Ah*Bl
                    MMA_TF32(acc[mt][nt], al, bh[nt]);   // Al*Bh
                }
            }
        }
        __syncthreads();
    }

    // store C
    #pragma unroll
    for (int mt = 0; mt < 4; mt++) {
        #pragma unroll
        for (int nt = 0; nt < 4; nt++) {
            int r = row0 + warpM + mt * 16 + gid;
            int cc = warpN + nt * 8 + tig * 2;
            if (r < n)
                *(float2*)(C + (size_t)r * HH + cc) =
                    make_float2(acc[mt][nt][0], acc[mt][nt][1]);
            if (r + 8 < n)
                *(float2*)(C + (size_t)(r + 8) * HH + cc) =
                    make_float2(acc[mt][nt][2], acc[mt][nt][3]);
        }
    }
}

// ---------------- fused aggregate + self-loop + bias + act + residual ----------------
template<int RELU, int RES>
__global__ __launch_bounds__(256)
void agg_k(const float* __restrict__ b, const float* __restrict__ rw,
           int out_sel, int n) {
    float* __restrict__ Xout = out_sel ? g_X2 : g_X1;
    const float* __restrict__ Xres = out_sel ? g_X1 : g_X2;
    const float* __restrict__ H = g_H;

    int node = blockIdx.x * (blockDim.x >> 5) + (threadIdx.x >> 5);
    if (node >= n) return;
    int lane = threadIdx.x & 31;
    int beg = __ldg(&g_off[node]);
    int end = __ldg(&g_off[node + 1]);

    float ax = 0.f, ay = 0.f, az = 0.f, aw = 0.f;
    int e = beg;
    for (; e + 1 < end; e += 2) {
        int   s0 = __ldg(&g_es[e]);
        int   s1 = __ldg(&g_es[e + 1]);
        float w0 = __ldg(&g_en[e]);
        float w1 = __ldg(&g_en[e + 1]);
        float4 v0 = *(const float4*)(H + (size_t)s0 * HH + lane * 4);
        float4 v1 = *(const float4*)(H + (size_t)s1 * HH + lane * 4);
        ax += w0 * v0.x + w1 * v1.x;
        ay += w0 * v0.y + w1 * v1.y;
        az += w0 * v0.z + w1 * v1.z;
        aw += w0 * v0.w + w1 * v1.w;
    }
    if (e < end) {
        int   s0 = __ldg(&g_es[e]);
        float w0 = __ldg(&g_en[e]);
        float4 v0 = *(const float4*)(H + (size_t)s0 * HH + lane * 4);
        ax += w0 * v0.x; ay += w0 * v0.y; az += w0 * v0.z; aw += w0 * v0.w;
    }

    float dv = __ldg(&g_dinv[node]);
    float sn = dv * dv;
    float4 h  = *(const float4*)(H + (size_t)node * HH + lane * 4);
    float4 bb = *(const float4*)(b + lane * 4);
    float vx = ax + sn * h.x + bb.x;
    float vy = ay + sn * h.y + bb.y;
    float vz = az + sn * h.z + bb.z;
    float vw = aw + sn * h.w + bb.w;
    if (RELU) {
        vx = fmaxf(vx, 0.f); vy = fmaxf(vy, 0.f);
        vz = fmaxf(vz, 0.f); vw = fmaxf(vw, 0.f);
    }
    if (RES) {
        float w = *rw;
        float4 r = *(const float4*)(Xres + (size_t)node * HH + lane * 4);
        vx += w * r.x; vy += w * r.y; vz += w * r.z; vw += w * r.w;
    }
    *(float4*)(Xout + (size_t)node * HH + lane * 4) = make_float4(vx, vy, vz, vw);
}

// ---------------- head: out[n,40] = g_X2[n,128] @ mlp_W[128,40] + b ----------------
__global__ void head_k(const float* __restrict__ W, const float* __restrict__ b,
                       float* __restrict__ out, int n) {
    int idx = blockIdx.x * blockDim.x + threadIdx.x;
    if (idx >= n * CC) return;
    int node = idx / CC;
    int c    = idx % CC;
    const float* xr = g_X2 + (size_t)node * HH;
    float a0 = 0.f, a1 = 0.f, a2 = 0.f, a3 = 0.f;
    #pragma unroll
    for (int k = 0; k < HH; k += 4) {
        a0 += xr[k + 0] * __ldg(W + (k + 0) * CC + c);
        a1 += xr[k + 1] * __ldg(W + (k + 1) * CC + c);
        a2 += xr[k + 2] * __ldg(W + (k + 2) * CC + c);
        a3 += xr[k + 3] * __ldg(W + (k + 3) * CC + c);
    }
    out[idx] = (a0 + a1) + (a2 + a3) + b[c];
}

// ---------------- launch: kernel launches ONLY, no runtime API calls ----------------
extern "C" void kernel_launch(void* const* d_in, const int* in_sizes, int n_in,
                              void* d_out, int out_size) {
    const float* X    = (const float*)d_in[0];
    const void*  ei   = d_in[1];
    const float* Ws   = (const float*)d_in[2];
    const float* bs   = (const float*)d_in[3];
    const float* mlpW = (const float*)d_in[4];
    const float* mlpb = (const float*)d_in[5];
    const float* rw   = (const float*)d_in[6];
    float* out = (float*)d_out;

    int n = in_sizes[0] / HH;
    int E = in_sizes[1] / 2;

    const int T = 256;

    // CSR build
    detect_k   <<<1, 1>>>(ei, E, n);
    zero_ints_k<<<(n + T - 1) / T, T>>>(n);
    hist_k     <<<(E + T - 1) / T, T>>>(ei, E);
    dinv_k     <<<(n + T - 1) / T, T>>>(n);
    scan_k     <<<1, 1024>>>(n);
    bucket_k   <<<(E + T - 1) / T, T>>>(ei, E);

    int gblocks = (n + 127) / 128;
    int ablocks = (n + 7) / 8;   // 8 warps per 256-thread block

    // layer 0: src = X, out -> g_X1, relu, no res
    gemm_tc_k<<<gblocks, T>>>(X, Ws + 0 * HH * HH, 0, n);
    agg_k<1, 0><<<ablocks, T>>>(bs + 0 * HH, rw, 0, n);
    // layer 1: src = g_X1, out -> g_X2, relu, res = g_X1
    gemm_tc_k<<<gblocks, T>>>(X, Ws + 1 * HH * HH, 1, n);
    agg_k<1, 1><<<ablocks, T>>>(bs + 1 * HH, rw, 1, n);
    // layer 2: src = g_X2, out -> g_X1, relu, res = g_X2
    gemm_tc_k<<<gblocks, T>>>(X, Ws + 2 * HH * HH, 2, n);
    agg_k<1, 1><<<ablocks, T>>>(bs + 2 * HH, rw, 0, n);
    // layer 3: src = g_X1, out -> g_X2, no relu, no res
    gemm_tc_k<<<gblocks, T>>>(X, Ws + 3 * HH * HH, 1, n);
    agg_k<0, 0><<<ablocks, T>>>(bs + 3 * HH, rw, 1, n);

    head_k<<<(n * CC + T - 1) / T, T>>>(mlpW, mlpb, out, n);
}

// round 11
// speedup vs baseline: 1.0243x; 1.0243x over previous
#include <cuda_runtime.h>
#include <cuda_bf16.h>
#include <stdint.h>

#define NMAX 50000
#define HH   128
#define EMAX 800000
#define CC   40

// ---------------- scratch (static device arrays; referenced directly in kernels) ----------------
__device__ int   g_is32;                  // 1 if edge_index is int32, 0 if int64
__device__ int   g_degi  [NMAX];
__device__ int   g_off   [NMAX + 1];
__device__ int   g_cursor[NMAX];
__device__ float g_dinv  [NMAX];
__device__ __align__(8) int2 g_edge[EMAX]; // (src, norm-bits) sorted by dst
__device__ __align__(16) float g_H [NMAX * HH];
__device__ __align__(16) float g_X1[NMAX * HH];
__device__ __align__(16) float g_X2[NMAX * HH];

// ---------------- edge access ----------------
__device__ __forceinline__ int edge_src(const void* ei, int E, int e) {
    return g_is32 ? ((const int*)ei)[e] : (int)((const long long*)ei)[e];
}
__device__ __forceinline__ int edge_dst(const void* ei, int E, int e) {
    return g_is32 ? ((const int*)ei)[E + e] : (int)((const long long*)ei)[E + e];
}

// ---------------- CSR build ----------------
// zero counters + parallel dtype detection (block 0, warp 0)
__global__ void init_k(const void* ei, int E, int n) {
    int i = blockIdx.x * blockDim.x + threadIdx.x;
    if (i < n) { g_degi[i] = 0; g_cursor[i] = 0; }
    if (blockIdx.x == 0 && threadIdx.x < 32) {
        // interpret first 32 entries as int64; any out-of-range => int32 data
        const long long* p = (const long long*)ei;
        int lim = (E < 32) ? E : 32;
        long long v = (threadIdx.x < lim) ? p[threadIdx.x] : 0;
        unsigned bad = __ballot_sync(0xffffffffu, v < 0 || v >= (long long)n);
        if (threadIdx.x == 0) g_is32 = bad ? 1 : 0;
    }
}

__global__ void hist_k(const void* ei, int E) {
    int e = blockIdx.x * blockDim.x + threadIdx.x;
    if (e < E) atomicAdd(&g_degi[edge_dst(ei, E, e)], 1);
}

// single-block exclusive scan over degrees; also computes dinv
__global__ void scan_k(int n) {
    __shared__ int shw[32];
    __shared__ int carry, btot;
    int tid = threadIdx.x, lane = tid & 31, wid = tid >> 5;
    if (tid == 0) carry = 0;
    __syncthreads();
    for (int base = 0; base < n; base += 1024) {
        int i = base + tid;
        int d = (i < n) ? g_degi[i] : 0;
        if (i < n) g_dinv[i] = rsqrtf((float)(d + 1));  // +1 self loop
        int incl = d;
        #pragma unroll
        for (int o = 1; o < 32; o <<= 1) {
            int v = __shfl_up_sync(0xffffffffu, incl, o);
            if (lane >= o) incl += v;
        }
        if (lane == 31) shw[wid] = incl;
        __syncthreads();
        if (wid == 0) {
            int w = shw[lane];
            int wi = w;
            #pragma unroll
            for (int o = 1; o < 32; o <<= 1) {
                int v = __shfl_up_sync(0xffffffffu, wi, o);
                if (lane >= o) wi += v;
            }
            shw[lane] = wi - w;
            if (lane == 31) btot = wi;
        }
        __syncthreads();
        if (i < n) g_off[i] = carry + shw[wid] + incl - d;
        __syncthreads();
        if (tid == 0) carry += btot;
        __syncthreads();
    }
    if (tid == 0) g_off[n] = carry;
}

__global__ void bucket_k(const void* ei, int E) {
    int e = blockIdx.x * blockDim.x + threadIdx.x;
    if (e >= E) return;
    int s = edge_src(ei, E, e);
    int d = edge_dst(ei, E, e);
    int pos = g_off[d] + atomicAdd(&g_cursor[d], 1);
    float w = g_dinv[s] * g_dinv[d];
    g_edge[pos] = make_int2(s, __float_as_int(w));
}

// ---------------- GEMM: g_H[n,128] = src[n,128] @ W[128,128] ----------------
// src_sel: 0 = external X, 1 = g_X1, 2 = g_X2
__global__ __launch_bounds__(256, 2)
void gemm128_k(const float* __restrict__ Xin, const float* __restrict__ W,
               int src_sel, int n) {
    const float* __restrict__ A = (src_sel == 0) ? Xin : (src_sel == 1 ? g_X1 : g_X2);
    float* __restrict__ C = g_H;

    __shared__ __align__(16) float As[32][132];
    __shared__ __align__(16) float Bs[32][128];
    const int tid  = threadIdx.x;
    const int row0 = blockIdx.x * 128;
    const int tm   = (tid >> 4) * 8;
    const int c0   = (tid & 15) * 4;

    float acc0[8][4] = {};
    float acc1[8][4] = {};

    for (int k0 = 0; k0 < HH; k0 += 32) {
        #pragma unroll
        for (int j = 0; j < 4; j++) {
            int t  = tid + j * 256;
            int r  = t >> 3;
            int kq = t & 7;
            float4 v = make_float4(0.f, 0.f, 0.f, 0.f);
            int grow = row0 + r;
            if (grow < n) v = *(const float4*)(A + (size_t)grow * HH + k0 + kq * 4);
            As[kq * 4 + 0][r] = v.x;
            As[kq * 4 + 1][r] = v.y;
            As[kq * 4 + 2][r] = v.z;
            As[kq * 4 + 3][r] = v.w;
        }
        #pragma unroll
        for (int j = 0; j < 4; j++) {
            int t  = tid + j * 256;
            int kr = t >> 5;
            int cq = t & 31;
            *(float4*)&Bs[kr][cq * 4] = *(const float4*)(W + (size_t)(k0 + kr) * HH + cq * 4);
        }
        __syncthreads();

        #pragma unroll
        for (int k = 0; k < 32; k++) {
            float4 b0 = *(const float4*)&Bs[k][c0];
            float4 b1 = *(const float4*)&Bs[k][c0 + 64];
            float4 a0 = *(const float4*)&As[k][tm];
            float4 a1 = *(const float4*)&As[k][tm + 4];
            float a[8] = {a0.x, a0.y, a0.z, a0.w, a1.x, a1.y, a1.z, a1.w};
            #pragma unroll
            for (int r = 0; r < 8; r++) {
                acc0[r][0] += a[r] * b0.x; acc0[r][1] += a[r] * b0.y;
                acc0[r][2] += a[r] * b0.z; acc0[r][3] += a[r] * b0.w;
                acc1[r][0] += a[r] * b1.x; acc1[r][1] += a[r] * b1.y;
                acc1[r][2] += a[r] * b1.z; acc1[r][3] += a[r] * b1.w;
            }
        }
        __syncthreads();
    }

    #pragma unroll
    for (int r = 0; r < 8; r++) {
        int grow = row0 + tm + r;
        if (grow < n) {
            *(float4*)(C + (size_t)grow * HH + c0) =
                make_float4(acc0[r][0], acc0[r][1], acc0[r][2], acc0[r][3]);
            *(float4*)(C + (size_t)grow * HH + c0 + 64) =
                make_float4(acc1[r][0], acc1[r][1], acc1[r][2], acc1[r][3]);
        }
    }
}

// ---------------- fused aggregate + self-loop + bias + act + residual ----------------
// warp per dst node; lane handles columns [lane*4, lane*4+4)
// out_sel: 0 -> write g_X1 (residual = g_X2), 1 -> write g_X2 (residual = g_X1)
template<int RELU, int RES>
__global__ __launch_bounds__(256)
void agg_k(const float* __restrict__ b, const float* __restrict__ rw,
           int out_sel, int n) {
    float* __restrict__ Xout = out_sel ? g_X2 : g_X1;
    const float* __restrict__ Xres = out_sel ? g_X1 : g_X2;
    const float* __restrict__ H = g_H;

    int node = blockIdx.x * (blockDim.x >> 5) + (threadIdx.x >> 5);
    if (node >= n) return;
    int lane = threadIdx.x & 31;
    int beg = __ldg(&g_off[node]);
    int end = __ldg(&g_off[node + 1]);

    float ax = 0.f, ay = 0.f, az = 0.f, aw = 0.f;
    int e = beg;
    for (; e + 1 < end; e += 2) {
        int2 e0 = __ldg(&g_edge[e]);
        int2 e1 = __ldg(&g_edge[e + 1]);
        float w0 = __int_as_float(e0.y);
        float w1 = __int_as_float(e1.y);
        float4 v0 = *(const float4*)(H + (size_t)e0.x * HH + lane * 4);
        float4 v1 = *(const float4*)(H + (size_t)e1.x * HH + lane * 4);
        ax += w0 * v0.x + w1 * v1.x;
        ay += w0 * v0.y + w1 * v1.y;
        az += w0 * v0.z + w1 * v1.z;
        aw += w0 * v0.w + w1 * v1.w;
    }
    if (e < end) {
        int2 e0 = __ldg(&g_edge[e]);
        float w0 = __int_as_float(e0.y);
        float4 v0 = *(const float4*)(H + (size_t)e0.x * HH + lane * 4);
        ax += w0 * v0.x; ay += w0 * v0.y; az += w0 * v0.z; aw += w0 * v0.w;
    }

    float dv = __ldg(&g_dinv[node]);
    float sn = dv * dv;
    float4 h  = *(const float4*)(H + (size_t)node * HH + lane * 4);
    float4 bb = *(const float4*)(b + lane * 4);
    float vx = ax + sn * h.x + bb.x;
    float vy = ay + sn * h.y + bb.y;
    float vz = az + sn * h.z + bb.z;
    float vw = aw + sn * h.w + bb.w;
    if (RELU) {
        vx = fmaxf(vx, 0.f); vy = fmaxf(vy, 0.f);
        vz = fmaxf(vz, 0.f); vw = fmaxf(vw, 0.f);
    }
    if (RES) {
        float w = *rw;
        float4 r = *(const float4*)(Xres + (size_t)node * HH + lane * 4);
        vx += w * r.x; vy += w * r.y; vz += w * r.z; vw += w * r.w;
    }
    *(float4*)(Xout + (size_t)node * HH + lane * 4) = make_float4(vx, vy, vz, vw);
}

// ---------------- head: out[n,40] = g_X2[n,128] @ mlp_W[128,40] + b ----------------
__global__ void head_k(const float* __restrict__ W, const float* __restrict__ b,
                       float* __restrict__ out, int n) {
    int idx = blockIdx.x * blockDim.x + threadIdx.x;
    if (idx >= n * CC) return;
    int node = idx / CC;
    int c    = idx % CC;
    const float* xr = g_X2 + (size_t)node * HH;
    float a0 = 0.f, a1 = 0.f, a2 = 0.f, a3 = 0.f;
    #pragma unroll
    for (int k = 0; k < HH; k += 4) {
        a0 += xr[k + 0] * __ldg(W + (k + 0) * CC + c);
        a1 += xr[k + 1] * __ldg(W + (k + 1) * CC + c);
        a2 += xr[k + 2] * __ldg(W + (k + 2) * CC + c);
        a3 += xr[k + 3] * __ldg(W + (k + 3) * CC + c);
    }
    out[idx] = (a0 + a1) + (a2 + a3) + b[c];
}

// ---------------- launch: kernel launches ONLY, no runtime API calls ----------------
extern "C" void kernel_launch(void* const* d_in, const int* in_sizes, int n_in,
                              void* d_out, int out_size) {
    const float* X    = (const float*)d_in[0];
    const void*  ei   = d_in[1];
    const float* Ws   = (const float*)d_in[2];
    const float* bs   = (const float*)d_in[3];
    const float* mlpW = (const float*)d_in[4];
    const float* mlpb = (const float*)d_in[5];
    const float* rw   = (const float*)d_in[6];
    float* out = (float*)d_out;

    int n = in_sizes[0] / HH;
    int E = in_sizes[1] / 2;

    const int T = 256;

    // CSR build: 4 launches
    init_k  <<<(n + T - 1) / T, T>>>(ei, E, n);
    hist_k  <<<(E + T - 1) / T, T>>>(ei, E);
    scan_k  <<<1, 1024>>>(n);
    bucket_k<<<(E + T - 1) / T, T>>>(ei, E);

    int gblocks = (n + 127) / 128;
    int ablocks = (n + 7) / 8;   // 8 warps per 256-thread block

    // layer 0: src = X, out -> g_X1, relu, no res
    gemm128_k<<<gblocks, T>>>(X, Ws + 0 * HH * HH, 0, n);
    agg_k<1, 0><<<ablocks, T>>>(bs + 0 * HH, rw, 0, n);
    // layer 1: src = g_X1, out -> g_X2, relu, res = g_X1
    gemm128_k<<<gblocks, T>>>(X, Ws + 1 * HH * HH, 1, n);
    agg_k<1, 1><<<ablocks, T>>>(bs + 1 * HH, rw, 1, n);
    // layer 2: src = g_X2, out -> g_X1, relu, res = g_X2
    gemm128_k<<<gblocks, T>>>(X, Ws + 2 * HH * HH, 2, n);
    agg_k<1, 1><<<ablocks, T>>>(bs + 2 * HH, rw, 0, n);
    // layer 3: src = g_X1, out -> g_X2, no relu, no res
    gemm128_k<<<gblocks, T>>>(X, Ws + 3 * HH * HH, 1, n);
    agg_k<0, 0><<<ablocks, T>>>(bs + 3 * HH, rw, 1, n);

    head_k<<<(n * CC + T - 1) / T, T>>>(mlpW, mlpb, out, n);
}